// round 4
// baseline (speedup 1.0000x reference)
#include <cuda_runtime.h>

// BilinearSampler: B=16, H=256, W=256, C=32, fp32, NHWC.
//
// R3: deepen MLP. 8 threads per pixel (one float4 each -> every corner read
// is one coalesced 128B line), 4 pixels per thread at stride total/4 so all
// 16 corner gathers are issued back-to-back before any is consumed.
// 32-bit offset arithmetic throughout (img is 134MB, fits easily).
// Streaming stores keep the write-once output from evicting gather-reused
// image lines in L2.

#define BS_B 16
#define BS_H 256
#define BS_W 256
#define BS_C 32          // floats per pixel
#define BS_C4 (BS_C / 4) // float4 per pixel = 8
#define PX_PER_THREAD 4

__global__ __launch_bounds__(256) void bilinear_sampler_kernel(
    const float* __restrict__ img,   // [B,H,W,C]
    const float* __restrict__ xs,    // [B,H,W]
    const float* __restrict__ ys,    // [B,H,W]
    float* __restrict__ out)         // [B,H,W,C]
{
    const unsigned total = (unsigned)BS_B * BS_H * BS_W * BS_C4; // 8,388,608
    const unsigned q     = total / PX_PER_THREAD;                // 2,097,152 (mult of 8)

    unsigned t = blockIdx.x * blockDim.x + threadIdx.x;
    if (t >= q) return;

    const int co = ((int)t & (BS_C4 - 1)) * 4;  // same for all 4 elements

    unsigned pix[PX_PER_THREAD];
    float xc[PX_PER_THREAD], yc[PX_PER_THREAD];

    // Batch all coordinate loads (8 independent 32-bit loads in flight).
#pragma unroll
    for (int i = 0; i < PX_PER_THREAD; i++) {
        unsigned e = t + (unsigned)i * q;
        pix[i] = e >> 3;
        xc[i] = __ldg(&xs[pix[i]]);
        yc[i] = __ldg(&ys[pix[i]]);
    }

    unsigned oa[PX_PER_THREAD], ob[PX_PER_THREAD], oc_[PX_PER_THREAD], od[PX_PER_THREAD];
    float wa[PX_PER_THREAD], wb[PX_PER_THREAD], wc[PX_PER_THREAD], wd[PX_PER_THREAD];

#pragma unroll
    for (int i = 0; i < PX_PER_THREAD; i++) {
        const float x = 0.5f * (xc[i] + 1.0f) * (float)(BS_W - 1);
        const float y = 0.5f * (yc[i] + 1.0f) * (float)(BS_H - 1);

        int x0 = __float2int_rd(x);
        int y0 = __float2int_rd(y);

        int x0c = min(max(x0, 0), BS_W - 1);
        int x1c = min(max(x0 + 1, 0), BS_W - 1);
        int y0c = min(max(y0, 0), BS_H - 1);
        int y1c = min(max(y0 + 1, 0), BS_H - 1);

        const float x0f = (float)x0c, x1f = (float)x1c;
        const float y0f = (float)y0c, y1f = (float)y1c;
        wa[i] = (x1f - x) * (y1f - y);
        wb[i] = (x1f - x) * (y - y0f);
        wc[i] = (x - x0f) * (y1f - y);
        wd[i] = (x - x0f) * (y - y0f);

        // 32-bit element offsets. batch = pix >> 16 (H*W = 65536).
        const unsigned bimg = (pix[i] >> 16) * (unsigned)(BS_H * BS_W * BS_C);
        oa[i]  = bimg + ((unsigned)(y0c * BS_W + x0c)) * BS_C + co;
        ob[i]  = bimg + ((unsigned)(y1c * BS_W + x0c)) * BS_C + co;
        oc_[i] = bimg + ((unsigned)(y0c * BS_W + x1c)) * BS_C + co;
        od[i]  = bimg + ((unsigned)(y1c * BS_W + x1c)) * BS_C + co;
    }

    // Issue all 16 corner gathers before consuming any (MLP = 16).
    float4 Ia[PX_PER_THREAD], Ib[PX_PER_THREAD], Ic[PX_PER_THREAD], Id[PX_PER_THREAD];
#pragma unroll
    for (int i = 0; i < PX_PER_THREAD; i++) {
        Ia[i] = __ldg((const float4*)&img[oa[i]]);
        Ib[i] = __ldg((const float4*)&img[ob[i]]);
        Ic[i] = __ldg((const float4*)&img[oc_[i]]);
        Id[i] = __ldg((const float4*)&img[od[i]]);
    }

#pragma unroll
    for (int i = 0; i < PX_PER_THREAD; i++) {
        float4 r;
        r.x = wa[i] * Ia[i].x + wb[i] * Ib[i].x + wc[i] * Ic[i].x + wd[i] * Id[i].x;
        r.y = wa[i] * Ia[i].y + wb[i] * Ib[i].y + wc[i] * Ic[i].y + wd[i] * Id[i].y;
        r.z = wa[i] * Ia[i].z + wb[i] * Ib[i].z + wc[i] * Ic[i].z + wd[i] * Id[i].z;
        r.w = wa[i] * Ia[i].w + wb[i] * Ib[i].w + wc[i] * Ic[i].w + wd[i] * Id[i].w;
        __stcs((float4*)&out[pix[i] * BS_C + co], r);
    }
}

extern "C" void kernel_launch(void* const* d_in, const int* in_sizes, int n_in,
                              void* d_out, int out_size) {
    const float* img = (const float*)d_in[0];
    const float* xs  = (const float*)d_in[1];
    const float* ys  = (const float*)d_in[2];
    float* out = (float*)d_out;

    const unsigned total = (unsigned)BS_B * BS_H * BS_W * BS_C4;
    const unsigned q     = total / PX_PER_THREAD;
    const int threads = 256;
    const int blocks = (int)((q + threads - 1) / threads);
    bilinear_sampler_kernel<<<blocks, threads>>>(img, xs, ys, out);
}